// round 12
// baseline (speedup 1.0000x reference)
#include <cuda_runtime.h>
#include <cuda_bf16.h>

#define D 128
#define HEADS 8
#define UNITS 16
#define MAX_NODES 50000
#define MAX_EDGES 800000
#define SCAN_BLK 1024
#define MAX_SCAN_BLOCKS ((MAX_NODES + SCAN_BLK - 1) / SCAN_BLK)

typedef unsigned long long ull;

// Scratch (device globals: no allocation allowed; zero-initialized at load)
__device__ float g_xp[MAX_NODES * D];        // projected features, 25.6 MB
__device__ int   g_deg[MAX_NODES];           // in-degree histogram (kept zeroed)
__device__ int   g_rowptr[MAX_NODES + 1];    // CSR row pointers (by target)
__device__ int   g_cursor[MAX_NODES];        // scatter cursors
__device__ int   g_csrc[MAX_EDGES];          // CSR: source node per slot
__device__ int   g_aggval[MAX_SCAN_BLOCKS];  // lookback: block aggregates
__device__ int   g_prefval[MAX_SCAN_BLOCKS]; // lookback: inclusive prefixes
__device__ int   g_state[MAX_SCAN_BLOCKS];   // lookback: 0/1/2 (kept zeroed)

// ---------------------------------------------------------------------------
// GEMM (side stream): g_xp[n][j] = sum_k x[n][k]*W[k][j], packed fma.rn.f32x2
// ---------------------------------------------------------------------------
__global__ void gemm_kernel(const float* __restrict__ x,
                            const float* __restrict__ W,
                            int n_nodes) {
    __shared__ ulonglong2 xs[32 * 32];  // 32 nodes x 128 floats, as 2x f32x2
    const int t = threadIdx.x;          // 0..127 output column
    const int n0 = blockIdx.x * 32;
    const int nrows = min(32, n_nodes - n0);

    const float4* x4 = reinterpret_cast<const float4*>(x);
#pragma unroll
    for (int q = 0; q < 8; q++) {
        int idx = q * 128 + t;
        int i = idx >> 5;
        int kq = idx & 31;
        float4 v = (i < nrows) ? x4[(size_t)(n0 + i) * 32 + kq]
                               : make_float4(0.f, 0.f, 0.f, 0.f);
        xs[idx] = *reinterpret_cast<ulonglong2*>(&v);
    }
    __syncthreads();

    ull acc2[32];
#pragma unroll
    for (int i = 0; i < 32; i++) acc2[i] = 0ull;  // {+0.f, +0.f}

    for (int kq = 0; kq < 32; kq++) {
        const float w0 = W[(4 * kq + 0) * D + t];
        const float w1 = W[(4 * kq + 1) * D + t];
        const float w2 = W[(4 * kq + 2) * D + t];
        const float w3 = W[(4 * kq + 3) * D + t];
        ull wp0, wp1;
        asm("mov.b64 %0, {%1,%2};" : "=l"(wp0) : "f"(w0), "f"(w1));
        asm("mov.b64 %0, {%1,%2};" : "=l"(wp1) : "f"(w2), "f"(w3));
#pragma unroll
        for (int i = 0; i < 32; i++) {
            ulonglong2 xv = xs[i * 32 + kq];  // broadcast across block
            asm("fma.rn.f32x2 %0, %1, %2, %0;" : "+l"(acc2[i]) : "l"(xv.x), "l"(wp0));
            asm("fma.rn.f32x2 %0, %1, %2, %0;" : "+l"(acc2[i]) : "l"(xv.y), "l"(wp1));
        }
    }

    for (int i = 0; i < nrows; i++) {
        float lo, hi;
        asm("mov.b64 {%0,%1}, %2;" : "=f"(lo), "=f"(hi) : "l"(acc2[i]));
        g_xp[(size_t)(n0 + i) * D + t] = lo + hi;
    }
}

// ---------------------------------------------------------------------------
// histogram of targets: 2 edges per thread (int4 load)
// ---------------------------------------------------------------------------
__global__ void hist_kernel(const int4* __restrict__ edges2, int n_edges) {
    int t = blockIdx.x * blockDim.x + threadIdx.x;
    int e = t * 2;
    if (e >= n_edges) return;
    int4 ed = edges2[t];  // two edges: (x,y), (z,w)
    atomicAdd(&g_deg[ed.y], 1);
    if (e + 1 < n_edges) atomicAdd(&g_deg[ed.w], 1);
}

// ---------------------------------------------------------------------------
// single-pass exclusive scan (decoupled lookback); restores g_deg = 0.
// 49 blocks, all resident in wave 1 -> lookback cannot deadlock.
// ---------------------------------------------------------------------------
__global__ void scan_onepass_kernel(int n_nodes, int n_edges) {
    __shared__ int wsum[32];
    __shared__ int s_excl;
    const int tid = threadIdx.x;
    const int lane = tid & 31;
    const int warp = tid >> 5;
    const int bid = blockIdx.x;
    const int i = bid * SCAN_BLK + tid;

    int v = (i < n_nodes) ? g_deg[i] : 0;
    if (i < n_nodes) g_deg[i] = 0;   // restore for next replay

    int incl = v;
#pragma unroll
    for (int off = 1; off < 32; off <<= 1) {
        int t = __shfl_up_sync(0xFFFFFFFFu, incl, off);
        if (lane >= off) incl += t;
    }
    if (lane == 31) wsum[warp] = incl;
    __syncthreads();
    if (warp == 0) {
        int wv = wsum[lane];
        int winc = wv;
#pragma unroll
        for (int off = 1; off < 32; off <<= 1) {
            int t = __shfl_up_sync(0xFFFFFFFFu, winc, off);
            if (lane >= off) winc += t;
        }
        wsum[lane] = winc - wv;  // exclusive warp offsets
        int tot = __shfl_sync(0xFFFFFFFFu, winc, 31);
        if (lane == 0) {
            g_aggval[bid] = tot;
            __threadfence();
            atomicExch(&g_state[bid], 1);
            int excl = 0;
            for (int p = bid - 1; p >= 0;) {
                int st;
                do { st = atomicAdd(&g_state[p], 0); } while (st == 0);
                if (st == 2) { excl += atomicAdd(&g_prefval[p], 0); break; }
                excl += atomicAdd(&g_aggval[p], 0);
                p--;
            }
            g_prefval[bid] = excl + tot;
            __threadfence();
            atomicExch(&g_state[bid], 2);
            s_excl = excl;
        }
    }
    __syncthreads();

    if (i < n_nodes) {
        int r = incl - v + wsum[warp] + s_excl;
        g_rowptr[i] = r;
        g_cursor[i] = r;
    }
    if (i == 0) g_rowptr[n_nodes] = n_edges;
}

// ---------------------------------------------------------------------------
// scatter: 2 edges per thread (int4 load); re-zero lookback state
// ---------------------------------------------------------------------------
__global__ void scatter_kernel(const int4* __restrict__ edges2, int n_edges) {
    int t = blockIdx.x * blockDim.x + threadIdx.x;
    if (t < MAX_SCAN_BLOCKS) g_state[t] = 0;
    int e = t * 2;
    if (e >= n_edges) return;
    int4 ed = edges2[t];  // two edges: (x,y), (z,w)
    int pos0 = atomicAdd(&g_cursor[ed.y], 1);
    g_csrc[pos0] = ed.x;
    if (e + 1 < n_edges) {
        int pos1 = atomicAdd(&g_cursor[ed.w], 1);
        g_csrc[pos1] = ed.z;
    }
}

// ---------------------------------------------------------------------------
// fused attention: one warp per target node, MLP=4 pipelined, packed f32x2.
//   lrelu(s) = 0.6s + 0.4|s|   (exact identity for slope 0.2)
//   score dot uses ka pre-scaled by {0.6,0.4}*log2e  ->  p = ex2(part)
//   out[tgt] = gelu( (sum_e p_e * xp[src_e]) / (sum_e p_e + 1e-7) + bias )
// ---------------------------------------------------------------------------
__device__ __forceinline__ float gelu_tanh(float v) {
    float c = 0.7978845608028654f * (v + 0.044715f * v * v * v);
    return 0.5f * v * (1.f + tanhf(c));
}

#define PACK2(out_, a_, b_) \
    asm("mov.b64 %0, {%1,%2};" : "=l"(out_) : "f"(a_), "f"(b_))
#define UNPACK2(a_, b_, in_) \
    asm("mov.b64 {%0,%1}, %2;" : "=f"(a_), "=f"(b_) : "l"(in_))
#define ADD2(out_, a_, b_) \
    asm("add.rn.f32x2 %0, %1, %2;" : "=l"(out_) : "l"(a_), "l"(b_))
#define MUL2(out_, a_, b_) \
    asm("mul.rn.f32x2 %0, %1, %2;" : "=l"(out_) : "l"(a_), "l"(b_))
#define FMA2(acc_, a_, b_) \
    asm("fma.rn.f32x2 %0, %1, %2, %0;" : "+l"(acc_) : "l"(a_), "l"(b_))
#define ABS2(out_, in_) \
    asm("and.b64 %0, %1, 0x7FFFFFFF7FFFFFFF;" : "=l"(out_) : "l"(in_))

__global__ void __launch_bounds__(256, 5)
attn_kernel(const float* __restrict__ ka1,
            const float* __restrict__ battn,
            const float* __restrict__ bias,
            float* __restrict__ out,
            int n_nodes) {
    int w = (blockIdx.x * blockDim.x + threadIdx.x) >> 5;
    if (w >= n_nodes) return;
    const int lane = threadIdx.x & 31;
    const int j = lane * 4;

    const int row = __ldg(&g_rowptr[w]);
    const int end = __ldg(&g_rowptr[w + 1]);

    const float4 xt = *reinterpret_cast<const float4*>(&g_xp[(size_t)w * D + j]);
    const float4 kb = *reinterpret_cast<const float4*>(&battn[j]);
    const float4 ka = *reinterpret_cast<const float4*>(&ka1[j]);

    const float LOG2E = 1.4426950408889634f;
    // tb = xt + 2*kb, packed
    ull tb01, tb23;
    PACK2(tb01, xt.x + 2.f * kb.x, xt.y + 2.f * kb.y);
    PACK2(tb23, xt.z + 2.f * kb.z, xt.w + 2.f * kb.w);
    // ka pre-scaled: 0.6*log2e and 0.4*log2e
    ull k6_01, k6_23, k4_01, k4_23;
    PACK2(k6_01, 0.6f * LOG2E * ka.x, 0.6f * LOG2E * ka.y);
    PACK2(k6_23, 0.6f * LOG2E * ka.z, 0.6f * LOG2E * ka.w);
    PACK2(k4_01, 0.4f * LOG2E * ka.x, 0.4f * LOG2E * ka.y);
    PACK2(k4_23, 0.4f * LOG2E * ka.z, 0.4f * LOG2E * ka.w);

    ull a01 = 0ull, a23 = 0ull;  // packed accumulators {+0,+0}
    float ssum = 0.f;

    auto process = [&](ulonglong2 xv2) {
        ull s01, s23, t01, t23, d;
        ADD2(s01, xv2.x, tb01);
        ADD2(s23, xv2.y, tb23);
        ABS2(t01, s01);
        ABS2(t23, s23);
        MUL2(d, s01, k6_01);
        FMA2(d, s23, k6_23);
        FMA2(d, t01, k4_01);
        FMA2(d, t23, k4_23);
        float lo, hi;
        UNPACK2(lo, hi, d);
        float part = lo + hi;           // = log2e * sum_units ka*lrelu(s)
        part += __shfl_xor_sync(0xFFFFFFFFu, part, 1);
        part += __shfl_xor_sync(0xFFFFFFFFu, part, 2);
        float p;
        asm("ex2.approx.ftz.f32 %0, %1;" : "=f"(p) : "f"(part));
        ssum += p;
        ull pp;
        PACK2(pp, p, p);
        FMA2(a01, pp, xv2.x);
        FMA2(a23, pp, xv2.y);
    };

    const ulonglong2* xp2 = reinterpret_cast<const ulonglong2*>(g_xp);
    int e = row;
    // pipelined main loop: batch 4 indices, issue 4 independent gathers
    for (; e + 4 <= end; e += 4) {
        int s0i = __ldg(&g_csrc[e + 0]);
        int s1i = __ldg(&g_csrc[e + 1]);
        int s2i = __ldg(&g_csrc[e + 2]);
        int s3i = __ldg(&g_csrc[e + 3]);
        ulonglong2 v0 = xp2[(size_t)s0i * 32 + lane];
        ulonglong2 v1 = xp2[(size_t)s1i * 32 + lane];
        ulonglong2 v2 = xp2[(size_t)s2i * 32 + lane];
        ulonglong2 v3 = xp2[(size_t)s3i * 32 + lane];
        process(v0);
        process(v1);
        process(v2);
        process(v3);
    }
    for (; e < end; e++) {
        int si = __ldg(&g_csrc[e]);
        process(xp2[(size_t)si * 32 + lane]);
    }

    const float inv = 1.f / (ssum + 1e-7f);
    float a0, a1, a2, a3;
    UNPACK2(a0, a1, a01);
    UNPACK2(a2, a3, a23);
    const float4 b = *reinterpret_cast<const float4*>(&bias[j]);
    float4 o;
    o.x = gelu_tanh(fmaf(a0, inv, b.x));
    o.y = gelu_tanh(fmaf(a1, inv, b.y));
    o.z = gelu_tanh(fmaf(a2, inv, b.z));
    o.w = gelu_tanh(fmaf(a3, inv, b.w));
    *reinterpret_cast<float4*>(&out[(size_t)w * D + j]) = o;
}

// ---------------------------------------------------------------------------
extern "C" void kernel_launch(void* const* d_in, const int* in_sizes, int n_in,
                              void* d_out, int out_size) {
    const float* x     = (const float*)d_in[0];
    const int*   edges = (const int*)d_in[1];
    const float* W     = (const float*)d_in[2]; // (D, H, U) row-major == D x 128
    const float* ka1   = (const float*)d_in[3];
    const float* battn = (const float*)d_in[4];
    const float* bias  = (const float*)d_in[5];
    float* out = (float*)d_out;

    const int n_nodes = in_sizes[0] / D;
    const int n_edges = in_sizes[1] / 2;
    const int nb = (n_nodes + SCAN_BLK - 1) / SCAN_BLK;
    const int npair = (n_edges + 1) / 2;

    // One-time host-side stream/event setup (first call is the non-captured
    // correctness run; capture calls reuse these). No device allocations.
    static cudaStream_t s_side = nullptr;
    static cudaEvent_t ev_fork = nullptr, ev_join = nullptr;
    if (s_side == nullptr) {
        cudaStreamCreateWithFlags(&s_side, cudaStreamNonBlocking);
        cudaEventCreateWithFlags(&ev_fork, cudaEventDisableTiming);
        cudaEventCreateWithFlags(&ev_join, cudaEventDisableTiming);
    }

    // Fork: gemm on side stream, CSR build on main stream (independent).
    cudaEventRecord(ev_fork, 0);
    cudaStreamWaitEvent(s_side, ev_fork, 0);
    gemm_kernel<<<(n_nodes + 31) / 32, 128, 0, s_side>>>(x, W, n_nodes);
    cudaEventRecord(ev_join, s_side);

    // Main stream: in-degree histogram -> scan -> scatter
    hist_kernel<<<(npair + 255) / 256, 256>>>((const int4*)edges, n_edges);
    scan_onepass_kernel<<<nb, SCAN_BLK>>>(n_nodes, n_edges);
    scatter_kernel<<<(npair + 255) / 256, 256>>>((const int4*)edges, n_edges);

    // Join: attn needs both g_xp (gemm) and CSR (scatter)
    cudaStreamWaitEvent(0, ev_join, 0);
    {
        int threads = 256;
        int blocks = (n_nodes * 32 + threads - 1) / threads;
        attn_kernel<<<blocks, threads>>>(ka1, battn, bias, out, n_nodes);
    }
}

// round 14
// speedup vs baseline: 1.4109x; 1.4109x over previous
#include <cuda_runtime.h>
#include <cuda_bf16.h>

#define D 128
#define HEADS 8
#define UNITS 16
#define MAX_NODES 50000
#define MAX_EDGES 800000
#define SCAN_BLK 1024
#define MAX_SCAN_BLOCKS ((MAX_NODES + SCAN_BLK - 1) / SCAN_BLK)

typedef unsigned long long ull;

// Scratch (device globals: no allocation allowed; zero-initialized at load)
__device__ float g_xp[MAX_NODES * D];        // projected features, 25.6 MB
__device__ int   g_deg[MAX_NODES];           // in-degree histogram (kept zeroed)
__device__ int   g_rowptr[MAX_NODES + 1];    // CSR row pointers (by target)
__device__ int   g_cursor[MAX_NODES];        // scatter cursors
__device__ int   g_csrc[MAX_EDGES];          // CSR: source node per slot
__device__ int   g_aggval[MAX_SCAN_BLOCKS];  // lookback: block aggregates
__device__ int   g_prefval[MAX_SCAN_BLOCKS]; // lookback: inclusive prefixes
__device__ int   g_state[MAX_SCAN_BLOCKS];   // lookback: 0/1/2 (kept zeroed)

// ---------------------------------------------------------------------------
// GEMM (side stream): g_xp[n][j] = sum_k x[n][k]*W[k][j], packed fma.rn.f32x2
// ---------------------------------------------------------------------------
__global__ void gemm_kernel(const float* __restrict__ x,
                            const float* __restrict__ W,
                            int n_nodes) {
    __shared__ ulonglong2 xs[32 * 32];  // 32 nodes x 128 floats, as 2x f32x2
    const int t = threadIdx.x;          // 0..127 output column
    const int n0 = blockIdx.x * 32;
    const int nrows = min(32, n_nodes - n0);

    const float4* x4 = reinterpret_cast<const float4*>(x);
#pragma unroll
    for (int q = 0; q < 8; q++) {
        int idx = q * 128 + t;
        int i = idx >> 5;
        int kq = idx & 31;
        float4 v = (i < nrows) ? x4[(size_t)(n0 + i) * 32 + kq]
                               : make_float4(0.f, 0.f, 0.f, 0.f);
        xs[idx] = *reinterpret_cast<ulonglong2*>(&v);
    }
    __syncthreads();

    ull acc2[32];
#pragma unroll
    for (int i = 0; i < 32; i++) acc2[i] = 0ull;  // {+0.f, +0.f}

    for (int kq = 0; kq < 32; kq++) {
        const float w0 = W[(4 * kq + 0) * D + t];
        const float w1 = W[(4 * kq + 1) * D + t];
        const float w2 = W[(4 * kq + 2) * D + t];
        const float w3 = W[(4 * kq + 3) * D + t];
        ull wp0, wp1;
        asm("mov.b64 %0, {%1,%2};" : "=l"(wp0) : "f"(w0), "f"(w1));
        asm("mov.b64 %0, {%1,%2};" : "=l"(wp1) : "f"(w2), "f"(w3));
#pragma unroll
        for (int i = 0; i < 32; i++) {
            ulonglong2 xv = xs[i * 32 + kq];  // broadcast across block
            asm("fma.rn.f32x2 %0, %1, %2, %0;" : "+l"(acc2[i]) : "l"(xv.x), "l"(wp0));
            asm("fma.rn.f32x2 %0, %1, %2, %0;" : "+l"(acc2[i]) : "l"(xv.y), "l"(wp1));
        }
    }

    for (int i = 0; i < nrows; i++) {
        float lo, hi;
        asm("mov.b64 {%0,%1}, %2;" : "=f"(lo), "=f"(hi) : "l"(acc2[i]));
        g_xp[(size_t)(n0 + i) * D + t] = lo + hi;
    }
}

// ---------------------------------------------------------------------------
// histogram of targets (int2 edge load, one edge per thread)
// ---------------------------------------------------------------------------
__global__ void hist_kernel(const int2* __restrict__ edges, int n_edges) {
    int e = blockIdx.x * blockDim.x + threadIdx.x;
    if (e >= n_edges) return;
    atomicAdd(&g_deg[edges[e].y], 1);
}

// ---------------------------------------------------------------------------
// single-pass exclusive scan (decoupled lookback); restores g_deg = 0.
// 49 blocks, all resident in wave 1 -> lookback cannot deadlock.
// ---------------------------------------------------------------------------
__global__ void scan_onepass_kernel(int n_nodes, int n_edges) {
    __shared__ int wsum[32];
    __shared__ int s_excl;
    const int tid = threadIdx.x;
    const int lane = tid & 31;
    const int warp = tid >> 5;
    const int bid = blockIdx.x;
    const int i = bid * SCAN_BLK + tid;

    int v = (i < n_nodes) ? g_deg[i] : 0;
    if (i < n_nodes) g_deg[i] = 0;   // restore for next replay

    int incl = v;
#pragma unroll
    for (int off = 1; off < 32; off <<= 1) {
        int t = __shfl_up_sync(0xFFFFFFFFu, incl, off);
        if (lane >= off) incl += t;
    }
    if (lane == 31) wsum[warp] = incl;
    __syncthreads();
    if (warp == 0) {
        int wv = wsum[lane];
        int winc = wv;
#pragma unroll
        for (int off = 1; off < 32; off <<= 1) {
            int t = __shfl_up_sync(0xFFFFFFFFu, winc, off);
            if (lane >= off) winc += t;
        }
        wsum[lane] = winc - wv;  // exclusive warp offsets
        int tot = __shfl_sync(0xFFFFFFFFu, winc, 31);
        if (lane == 0) {
            g_aggval[bid] = tot;
            __threadfence();
            atomicExch(&g_state[bid], 1);
            int excl = 0;
            for (int p = bid - 1; p >= 0;) {
                int st;
                do { st = atomicAdd(&g_state[p], 0); } while (st == 0);
                if (st == 2) { excl += atomicAdd(&g_prefval[p], 0); break; }
                excl += atomicAdd(&g_aggval[p], 0);
                p--;
            }
            g_prefval[bid] = excl + tot;
            __threadfence();
            atomicExch(&g_state[bid], 2);
            s_excl = excl;
        }
    }
    __syncthreads();

    if (i < n_nodes) {
        int r = incl - v + wsum[warp] + s_excl;
        g_rowptr[i] = r;
        g_cursor[i] = r;
    }
    if (i == 0) g_rowptr[n_nodes] = n_edges;
}

// ---------------------------------------------------------------------------
// scatter sources into CSR slots (int2, one edge per thread);
// re-zero lookback state for next replay
// ---------------------------------------------------------------------------
__global__ void scatter_kernel(const int2* __restrict__ edges, int n_edges) {
    int e = blockIdx.x * blockDim.x + threadIdx.x;
    if (e < MAX_SCAN_BLOCKS) g_state[e] = 0;
    if (e >= n_edges) return;
    int2 ed = edges[e];
    int pos = atomicAdd(&g_cursor[ed.y], 1);
    g_csrc[pos] = ed.x;
}

// ---------------------------------------------------------------------------
// fused attention: one warp per target node, MLP=4 pipelined, packed f32x2.
//   lrelu(s) = 0.6s + 0.4|s|   (exact identity for slope 0.2)
//   score dot uses ka pre-scaled by {0.6,0.4}*log2e  ->  p = ex2(part)
//   out[tgt] = gelu( (sum_e p_e * xp[src_e]) / (sum_e p_e + 1e-7) + bias )
// NO launch_bounds: natural 52 regs; capping to 51 caused hot-loop spills.
// ---------------------------------------------------------------------------
__device__ __forceinline__ float gelu_tanh(float v) {
    float c = 0.7978845608028654f * (v + 0.044715f * v * v * v);
    return 0.5f * v * (1.f + tanhf(c));
}

#define PACK2(out_, a_, b_) \
    asm("mov.b64 %0, {%1,%2};" : "=l"(out_) : "f"(a_), "f"(b_))
#define UNPACK2(a_, b_, in_) \
    asm("mov.b64 {%0,%1}, %2;" : "=f"(a_), "=f"(b_) : "l"(in_))
#define ADD2(out_, a_, b_) \
    asm("add.rn.f32x2 %0, %1, %2;" : "=l"(out_) : "l"(a_), "l"(b_))
#define MUL2(out_, a_, b_) \
    asm("mul.rn.f32x2 %0, %1, %2;" : "=l"(out_) : "l"(a_), "l"(b_))
#define FMA2(acc_, a_, b_) \
    asm("fma.rn.f32x2 %0, %1, %2, %0;" : "+l"(acc_) : "l"(a_), "l"(b_))
#define ABS2(out_, in_) \
    asm("and.b64 %0, %1, 0x7FFFFFFF7FFFFFFF;" : "=l"(out_) : "l"(in_))

__global__ void attn_kernel(const float* __restrict__ ka1,
                            const float* __restrict__ battn,
                            const float* __restrict__ bias,
                            float* __restrict__ out,
                            int n_nodes) {
    int w = (blockIdx.x * blockDim.x + threadIdx.x) >> 5;
    if (w >= n_nodes) return;
    const int lane = threadIdx.x & 31;
    const int j = lane * 4;

    const int row = __ldg(&g_rowptr[w]);
    const int end = __ldg(&g_rowptr[w + 1]);

    const float4 xt = *reinterpret_cast<const float4*>(&g_xp[(size_t)w * D + j]);
    const float4 kb = *reinterpret_cast<const float4*>(&battn[j]);
    const float4 ka = *reinterpret_cast<const float4*>(&ka1[j]);

    const float LOG2E = 1.4426950408889634f;
    // tb = xt + 2*kb, packed
    ull tb01, tb23;
    PACK2(tb01, xt.x + 2.f * kb.x, xt.y + 2.f * kb.y);
    PACK2(tb23, xt.z + 2.f * kb.z, xt.w + 2.f * kb.w);
    // ka pre-scaled: 0.6*log2e and 0.4*log2e
    ull k6_01, k6_23, k4_01, k4_23;
    PACK2(k6_01, 0.6f * LOG2E * ka.x, 0.6f * LOG2E * ka.y);
    PACK2(k6_23, 0.6f * LOG2E * ka.z, 0.6f * LOG2E * ka.w);
    PACK2(k4_01, 0.4f * LOG2E * ka.x, 0.4f * LOG2E * ka.y);
    PACK2(k4_23, 0.4f * LOG2E * ka.z, 0.4f * LOG2E * ka.w);

    ull a01 = 0ull, a23 = 0ull;  // packed accumulators {+0,+0}
    float ssum = 0.f;

    auto process = [&](ulonglong2 xv2) {
        ull s01, s23, t01, t23, d;
        ADD2(s01, xv2.x, tb01);
        ADD2(s23, xv2.y, tb23);
        ABS2(t01, s01);
        ABS2(t23, s23);
        MUL2(d, s01, k6_01);
        FMA2(d, s23, k6_23);
        FMA2(d, t01, k4_01);
        FMA2(d, t23, k4_23);
        float lo, hi;
        UNPACK2(lo, hi, d);
        float part = lo + hi;           // = log2e * sum_units ka*lrelu(s)
        part += __shfl_xor_sync(0xFFFFFFFFu, part, 1);
        part += __shfl_xor_sync(0xFFFFFFFFu, part, 2);
        float p;
        asm("ex2.approx.ftz.f32 %0, %1;" : "=f"(p) : "f"(part));
        ssum += p;
        ull pp;
        PACK2(pp, p, p);
        FMA2(a01, pp, xv2.x);
        FMA2(a23, pp, xv2.y);
    };

    const ulonglong2* xp2 = reinterpret_cast<const ulonglong2*>(g_xp);
    int e = row;
    // pipelined main loop: batch 4 indices, issue 4 independent gathers
    for (; e + 4 <= end; e += 4) {
        int s0i = __ldg(&g_csrc[e + 0]);
        int s1i = __ldg(&g_csrc[e + 1]);
        int s2i = __ldg(&g_csrc[e + 2]);
        int s3i = __ldg(&g_csrc[e + 3]);
        ulonglong2 v0 = xp2[(size_t)s0i * 32 + lane];
        ulonglong2 v1 = xp2[(size_t)s1i * 32 + lane];
        ulonglong2 v2 = xp2[(size_t)s2i * 32 + lane];
        ulonglong2 v3 = xp2[(size_t)s3i * 32 + lane];
        process(v0);
        process(v1);
        process(v2);
        process(v3);
    }
    for (; e < end; e++) {
        int si = __ldg(&g_csrc[e]);
        process(xp2[(size_t)si * 32 + lane]);
    }

    const float inv = 1.f / (ssum + 1e-7f);
    float a0, a1, a2, a3;
    UNPACK2(a0, a1, a01);
    UNPACK2(a2, a3, a23);
    const float4 b = *reinterpret_cast<const float4*>(&bias[j]);
    float4 o;
    o.x = gelu_tanh(fmaf(a0, inv, b.x));
    o.y = gelu_tanh(fmaf(a1, inv, b.y));
    o.z = gelu_tanh(fmaf(a2, inv, b.z));
    o.w = gelu_tanh(fmaf(a3, inv, b.w));
    *reinterpret_cast<float4*>(&out[(size_t)w * D + j]) = o;
}

// ---------------------------------------------------------------------------
extern "C" void kernel_launch(void* const* d_in, const int* in_sizes, int n_in,
                              void* d_out, int out_size) {
    const float* x     = (const float*)d_in[0];
    const int*   edges = (const int*)d_in[1];
    const float* W     = (const float*)d_in[2]; // (D, H, U) row-major == D x 128
    const float* ka1   = (const float*)d_in[3];
    const float* battn = (const float*)d_in[4];
    const float* bias  = (const float*)d_in[5];
    float* out = (float*)d_out;

    const int n_nodes = in_sizes[0] / D;
    const int n_edges = in_sizes[1] / 2;
    const int nb = (n_nodes + SCAN_BLK - 1) / SCAN_BLK;

    // One-time host-side stream/event setup (first call is the non-captured
    // correctness run; capture calls reuse these). No device allocations.
    static cudaStream_t s_side = nullptr;
    static cudaEvent_t ev_fork = nullptr, ev_join = nullptr;
    if (s_side == nullptr) {
        cudaStreamCreateWithFlags(&s_side, cudaStreamNonBlocking);
        cudaEventCreateWithFlags(&ev_fork, cudaEventDisableTiming);
        cudaEventCreateWithFlags(&ev_join, cudaEventDisableTiming);
    }

    // Fork: gemm on side stream, CSR build on main stream (independent).
    cudaEventRecord(ev_fork, 0);
    cudaStreamWaitEvent(s_side, ev_fork, 0);
    gemm_kernel<<<(n_nodes + 31) / 32, 128, 0, s_side>>>(x, W, n_nodes);
    cudaEventRecord(ev_join, s_side);

    // Main stream: in-degree histogram -> scan -> scatter
    hist_kernel<<<(n_edges + 255) / 256, 256>>>((const int2*)edges, n_edges);
    scan_onepass_kernel<<<nb, SCAN_BLK>>>(n_nodes, n_edges);
    scatter_kernel<<<(n_edges + 255) / 256, 256>>>((const int2*)edges, n_edges);

    // Join: attn needs both g_xp (gemm) and CSR (scatter)
    cudaStreamWaitEvent(0, ev_join, 0);
    {
        int threads = 256;
        int blocks = (n_nodes * 32 + threads - 1) / threads;
        attn_kernel<<<blocks, threads>>>(ka1, battn, bias, out, n_nodes);
    }
}

// round 15
// speedup vs baseline: 1.5177x; 1.0757x over previous
#include <cuda_runtime.h>
#include <cuda_fp16.h>
#include <cuda_bf16.h>

#define D 128
#define HEADS 8
#define UNITS 16
#define MAX_NODES 50000
#define MAX_EDGES 800000
#define SCAN_BLK 1024
#define MAX_SCAN_BLOCKS ((MAX_NODES + SCAN_BLK - 1) / SCAN_BLK)

typedef unsigned long long ull;

// Scratch (device globals: no allocation allowed; zero-initialized at load)
__device__ __half g_xph[MAX_NODES * D];      // projected features, fp16, 12.8 MB
__device__ int    g_deg[MAX_NODES];          // in-degree histogram (kept zeroed)
__device__ int    g_rowptr[MAX_NODES + 1];   // CSR row pointers (by target)
__device__ int    g_cursor[MAX_NODES];       // scatter cursors
__device__ int    g_csrc[MAX_EDGES];         // CSR: source node per slot
__device__ int    g_aggval[MAX_SCAN_BLOCKS]; // lookback: block aggregates
__device__ int    g_prefval[MAX_SCAN_BLOCKS];// lookback: inclusive prefixes
__device__ int    g_state[MAX_SCAN_BLOCKS];  // lookback: 0/1/2 (kept zeroed)

// ---------------------------------------------------------------------------
// GEMM (side stream): g_xph[n][j] = fp16( sum_k x[n][k]*W[k][j] ),
// packed fma.rn.f32x2 accumulation in fp32.
// ---------------------------------------------------------------------------
__global__ void gemm_kernel(const float* __restrict__ x,
                            const float* __restrict__ W,
                            int n_nodes) {
    __shared__ ulonglong2 xs[32 * 32];  // 32 nodes x 128 floats, as 2x f32x2
    const int t = threadIdx.x;          // 0..127 output column
    const int n0 = blockIdx.x * 32;
    const int nrows = min(32, n_nodes - n0);

    const float4* x4 = reinterpret_cast<const float4*>(x);
#pragma unroll
    for (int q = 0; q < 8; q++) {
        int idx = q * 128 + t;
        int i = idx >> 5;
        int kq = idx & 31;
        float4 v = (i < nrows) ? x4[(size_t)(n0 + i) * 32 + kq]
                               : make_float4(0.f, 0.f, 0.f, 0.f);
        xs[idx] = *reinterpret_cast<ulonglong2*>(&v);
    }
    __syncthreads();

    ull acc2[32];
#pragma unroll
    for (int i = 0; i < 32; i++) acc2[i] = 0ull;  // {+0.f, +0.f}

    for (int kq = 0; kq < 32; kq++) {
        const float w0 = W[(4 * kq + 0) * D + t];
        const float w1 = W[(4 * kq + 1) * D + t];
        const float w2 = W[(4 * kq + 2) * D + t];
        const float w3 = W[(4 * kq + 3) * D + t];
        ull wp0, wp1;
        asm("mov.b64 %0, {%1,%2};" : "=l"(wp0) : "f"(w0), "f"(w1));
        asm("mov.b64 %0, {%1,%2};" : "=l"(wp1) : "f"(w2), "f"(w3));
#pragma unroll
        for (int i = 0; i < 32; i++) {
            ulonglong2 xv = xs[i * 32 + kq];  // broadcast across block
            asm("fma.rn.f32x2 %0, %1, %2, %0;" : "+l"(acc2[i]) : "l"(xv.x), "l"(wp0));
            asm("fma.rn.f32x2 %0, %1, %2, %0;" : "+l"(acc2[i]) : "l"(xv.y), "l"(wp1));
        }
    }

    for (int i = 0; i < nrows; i++) {
        float lo, hi;
        asm("mov.b64 {%0,%1}, %2;" : "=f"(lo), "=f"(hi) : "l"(acc2[i]));
        g_xph[(size_t)(n0 + i) * D + t] = __float2half_rn(lo + hi);
    }
}

// ---------------------------------------------------------------------------
// histogram of targets (int2 edge load, one edge per thread)
// ---------------------------------------------------------------------------
__global__ void hist_kernel(const int2* __restrict__ edges, int n_edges) {
    int e = blockIdx.x * blockDim.x + threadIdx.x;
    if (e >= n_edges) return;
    atomicAdd(&g_deg[edges[e].y], 1);
}

// ---------------------------------------------------------------------------
// single-pass exclusive scan (decoupled lookback); restores g_deg = 0.
// 49 blocks, all resident in wave 1 -> lookback cannot deadlock.
// ---------------------------------------------------------------------------
__global__ void scan_onepass_kernel(int n_nodes, int n_edges) {
    __shared__ int wsum[32];
    __shared__ int s_excl;
    const int tid = threadIdx.x;
    const int lane = tid & 31;
    const int warp = tid >> 5;
    const int bid = blockIdx.x;
    const int i = bid * SCAN_BLK + tid;

    int v = (i < n_nodes) ? g_deg[i] : 0;
    if (i < n_nodes) g_deg[i] = 0;   // restore for next replay

    int incl = v;
#pragma unroll
    for (int off = 1; off < 32; off <<= 1) {
        int t = __shfl_up_sync(0xFFFFFFFFu, incl, off);
        if (lane >= off) incl += t;
    }
    if (lane == 31) wsum[warp] = incl;
    __syncthreads();
    if (warp == 0) {
        int wv = wsum[lane];
        int winc = wv;
#pragma unroll
        for (int off = 1; off < 32; off <<= 1) {
            int t = __shfl_up_sync(0xFFFFFFFFu, winc, off);
            if (lane >= off) winc += t;
        }
        wsum[lane] = winc - wv;  // exclusive warp offsets
        int tot = __shfl_sync(0xFFFFFFFFu, winc, 31);
        if (lane == 0) {
            g_aggval[bid] = tot;
            __threadfence();
            atomicExch(&g_state[bid], 1);
            int excl = 0;
            for (int p = bid - 1; p >= 0;) {
                int st;
                do { st = atomicAdd(&g_state[p], 0); } while (st == 0);
                if (st == 2) { excl += atomicAdd(&g_prefval[p], 0); break; }
                excl += atomicAdd(&g_aggval[p], 0);
                p--;
            }
            g_prefval[bid] = excl + tot;
            __threadfence();
            atomicExch(&g_state[bid], 2);
            s_excl = excl;
        }
    }
    __syncthreads();

    if (i < n_nodes) {
        int r = incl - v + wsum[warp] + s_excl;
        g_rowptr[i] = r;
        g_cursor[i] = r;
    }
    if (i == 0) g_rowptr[n_nodes] = n_edges;
}

// ---------------------------------------------------------------------------
// scatter sources into CSR slots (int2, one edge per thread);
// re-zero lookback state for next replay
// ---------------------------------------------------------------------------
__global__ void scatter_kernel(const int2* __restrict__ edges, int n_edges) {
    int e = blockIdx.x * blockDim.x + threadIdx.x;
    if (e < MAX_SCAN_BLOCKS) g_state[e] = 0;
    if (e >= n_edges) return;
    int2 ed = edges[e];
    int pos = atomicAdd(&g_cursor[ed.y], 1);
    g_csrc[pos] = ed.x;
}

// ---------------------------------------------------------------------------
// fused attention: one warp per target node, MLP=4 pipelined, fp16 gathers.
//   lrelu(s) = 0.6s + 0.4|s|   (exact identity for slope 0.2)
//   score dot uses ka pre-scaled by {0.6,0.4}*log2e  ->  p = ex2(part)
//   out[tgt] = gelu( (sum_e p_e * xp[src_e]) / (sum_e p_e + 1e-7) + bias )
// NO launch_bounds: natural regs; capping caused hot-loop spills (R12).
// ---------------------------------------------------------------------------
__device__ __forceinline__ float gelu_tanh(float v) {
    float c = 0.7978845608028654f * (v + 0.044715f * v * v * v);
    return 0.5f * v * (1.f + tanhf(c));
}

#define PACK2(out_, a_, b_) \
    asm("mov.b64 %0, {%1,%2};" : "=l"(out_) : "f"(a_), "f"(b_))
#define UNPACK2(a_, b_, in_) \
    asm("mov.b64 {%0,%1}, %2;" : "=f"(a_), "=f"(b_) : "l"(in_))
#define ADD2(out_, a_, b_) \
    asm("add.rn.f32x2 %0, %1, %2;" : "=l"(out_) : "l"(a_), "l"(b_))
#define MUL2(out_, a_, b_) \
    asm("mul.rn.f32x2 %0, %1, %2;" : "=l"(out_) : "l"(a_), "l"(b_))
#define FMA2(acc_, a_, b_) \
    asm("fma.rn.f32x2 %0, %1, %2, %0;" : "+l"(acc_) : "l"(a_), "l"(b_))
#define ABS2(out_, in_) \
    asm("and.b64 %0, %1, 0x7FFFFFFF7FFFFFFF;" : "=l"(out_) : "l"(in_))

__global__ void attn_kernel(const float* __restrict__ ka1,
                            const float* __restrict__ battn,
                            const float* __restrict__ bias,
                            float* __restrict__ out,
                            int n_nodes) {
    int w = (blockIdx.x * blockDim.x + threadIdx.x) >> 5;
    if (w >= n_nodes) return;
    const int lane = threadIdx.x & 31;
    const int j = lane * 4;

    const int row = __ldg(&g_rowptr[w]);
    const int end = __ldg(&g_rowptr[w + 1]);

    const uint2* xp2 = reinterpret_cast<const uint2*>(g_xph); // 4 halves per uint2

    // target row (fp16 -> fp32)
    uint2 xtu = xp2[(size_t)w * 32 + lane];
    float2 xt01 = __half22float2(*reinterpret_cast<__half2*>(&xtu.x));
    float2 xt23 = __half22float2(*reinterpret_cast<__half2*>(&xtu.y));
    const float4 kb = *reinterpret_cast<const float4*>(&battn[j]);
    const float4 ka = *reinterpret_cast<const float4*>(&ka1[j]);

    const float LOG2E = 1.4426950408889634f;
    // tb = xt + 2*kb, packed
    ull tb01, tb23;
    PACK2(tb01, xt01.x + 2.f * kb.x, xt01.y + 2.f * kb.y);
    PACK2(tb23, xt23.x + 2.f * kb.z, xt23.y + 2.f * kb.w);
    // ka pre-scaled: 0.6*log2e and 0.4*log2e
    ull k6_01, k6_23, k4_01, k4_23;
    PACK2(k6_01, 0.6f * LOG2E * ka.x, 0.6f * LOG2E * ka.y);
    PACK2(k6_23, 0.6f * LOG2E * ka.z, 0.6f * LOG2E * ka.w);
    PACK2(k4_01, 0.4f * LOG2E * ka.x, 0.4f * LOG2E * ka.y);
    PACK2(k4_23, 0.4f * LOG2E * ka.z, 0.4f * LOG2E * ka.w);

    ull a01 = 0ull, a23 = 0ull;  // packed accumulators {+0,+0}
    float ssum = 0.f;

    auto process = [&](uint2 xu) {
        // fp16 -> fp32 (4 converts), then packed f32x2 math
        float2 f01 = __half22float2(*reinterpret_cast<__half2*>(&xu.x));
        float2 f23 = __half22float2(*reinterpret_cast<__half2*>(&xu.y));
        ull x01, x23;
        PACK2(x01, f01.x, f01.y);
        PACK2(x23, f23.x, f23.y);
        ull s01, s23, t01, t23, d;
        ADD2(s01, x01, tb01);
        ADD2(s23, x23, tb23);
        ABS2(t01, s01);
        ABS2(t23, s23);
        MUL2(d, s01, k6_01);
        FMA2(d, s23, k6_23);
        FMA2(d, t01, k4_01);
        FMA2(d, t23, k4_23);
        float lo, hi;
        UNPACK2(lo, hi, d);
        float part = lo + hi;           // = log2e * sum_units ka*lrelu(s)
        part += __shfl_xor_sync(0xFFFFFFFFu, part, 1);
        part += __shfl_xor_sync(0xFFFFFFFFu, part, 2);
        float p;
        asm("ex2.approx.ftz.f32 %0, %1;" : "=f"(p) : "f"(part));
        ssum += p;
        ull pp;
        PACK2(pp, p, p);
        FMA2(a01, pp, x01);
        FMA2(a23, pp, x23);
    };

    int e = row;
    // pipelined main loop: batch 4 indices, issue 4 independent 8B gathers
    for (; e + 4 <= end; e += 4) {
        int s0i = __ldg(&g_csrc[e + 0]);
        int s1i = __ldg(&g_csrc[e + 1]);
        int s2i = __ldg(&g_csrc[e + 2]);
        int s3i = __ldg(&g_csrc[e + 3]);
        uint2 v0 = xp2[(size_t)s0i * 32 + lane];
        uint2 v1 = xp2[(size_t)s1i * 32 + lane];
        uint2 v2 = xp2[(size_t)s2i * 32 + lane];
        uint2 v3 = xp2[(size_t)s3i * 32 + lane];
        process(v0);
        process(v1);
        process(v2);
        process(v3);
    }
    for (; e < end; e++) {
        int si = __ldg(&g_csrc[e]);
        process(xp2[(size_t)si * 32 + lane]);
    }

    const float inv = 1.f / (ssum + 1e-7f);
    float a0, a1, a2, a3;
    UNPACK2(a0, a1, a01);
    UNPACK2(a2, a3, a23);
    const float4 b = *reinterpret_cast<const float4*>(&bias[j]);
    float4 o;
    o.x = gelu_tanh(fmaf(a0, inv, b.x));
    o.y = gelu_tanh(fmaf(a1, inv, b.y));
    o.z = gelu_tanh(fmaf(a2, inv, b.z));
    o.w = gelu_tanh(fmaf(a3, inv, b.w));
    *reinterpret_cast<float4*>(&out[(size_t)w * D + j]) = o;
}

// ---------------------------------------------------------------------------
extern "C" void kernel_launch(void* const* d_in, const int* in_sizes, int n_in,
                              void* d_out, int out_size) {
    const float* x     = (const float*)d_in[0];
    const int*   edges = (const int*)d_in[1];
    const float* W     = (const float*)d_in[2]; // (D, H, U) row-major == D x 128
    const float* ka1   = (const float*)d_in[3];
    const float* battn = (const float*)d_in[4];
    const float* bias  = (const float*)d_in[5];
    float* out = (float*)d_out;

    const int n_nodes = in_sizes[0] / D;
    const int n_edges = in_sizes[1] / 2;
    const int nb = (n_nodes + SCAN_BLK - 1) / SCAN_BLK;

    // One-time host-side stream/event setup (first call is the non-captured
    // correctness run; capture calls reuse these). No device allocations.
    static cudaStream_t s_side = nullptr;
    static cudaEvent_t ev_fork = nullptr, ev_join = nullptr;
    if (s_side == nullptr) {
        cudaStreamCreateWithFlags(&s_side, cudaStreamNonBlocking);
        cudaEventCreateWithFlags(&ev_fork, cudaEventDisableTiming);
        cudaEventCreateWithFlags(&ev_join, cudaEventDisableTiming);
    }

    // Fork: gemm on side stream, CSR build on main stream (independent).
    cudaEventRecord(ev_fork, 0);
    cudaStreamWaitEvent(s_side, ev_fork, 0);
    gemm_kernel<<<(n_nodes + 31) / 32, 128, 0, s_side>>>(x, W, n_nodes);
    cudaEventRecord(ev_join, s_side);

    // Main stream: in-degree histogram -> scan -> scatter
    hist_kernel<<<(n_edges + 255) / 256, 256>>>((const int2*)edges, n_edges);
    scan_onepass_kernel<<<nb, SCAN_BLK>>>(n_nodes, n_edges);
    scatter_kernel<<<(n_edges + 255) / 256, 256>>>((const int2*)edges, n_edges);

    // Join: attn needs both g_xph (gemm) and CSR (scatter)
    cudaStreamWaitEvent(0, ev_join, 0);
    {
        int threads = 256;
        int blocks = (n_nodes * 32 + threads - 1) / threads;
        attn_kernel<<<blocks, threads>>>(ka1, battn, bias, out, n_nodes);
    }
}